// round 9
// baseline (speedup 1.0000x reference)
#include <cuda_runtime.h>
#include <cuda_bf16.h>

// AbsolutePositionEncoding: out[b, s, :] = E[s / 8, :]
//   x: [64, 2048] fp32 (shape only, unused)
//   E: [512, 256] fp32 (512 KiB — fits L1/L2, each line re-read ~512x)
//   out: [64, 2048, 256] fp32 (128 MiB — pure write-bandwidth roofline)
//
// Flat float4 index i over the output:
//   vec = i & 63; row = i >> 6; seq = row & 2047; obj = seq >> 3
// E read via __ldg (L1 path); output via __stcs streaming stores so the
// 128 MiB write stream does not evict the E table from L2.
//
// Grid is sized so blocks*threads*ITERS == TOTAL_VEC4 exactly: the per-thread
// loop has a compile-time trip count of 4, fully unrolled, with the 4
// independent LDG/STG.128 pairs front-batched (max MLP on the store path).

static constexpr int SEQ_LEN = 2048;
static constexpr int E_DIMS  = 256;
static constexpr int VECS_PER_ROW = E_DIMS / 4;   // 64 float4 per row
static constexpr long long TOTAL_VEC4 = 64LL * 2048 * VECS_PER_ROW; // 8,388,608

static constexpr int THREADS = 256;
static constexpr int BLOCKS  = 8192;
static constexpr int ITERS   = (int)(TOTAL_VEC4 / ((long long)THREADS * BLOCKS)); // 4
static_assert((long long)THREADS * BLOCKS * ITERS == TOTAL_VEC4, "exact cover");

__global__ __launch_bounds__(THREADS)
void ape_kernel(const float4* __restrict__ E4, float4* __restrict__ out4)
{
    const unsigned stride = BLOCKS * THREADS;           // 2,097,152 — fits u32
    unsigned i = blockIdx.x * THREADS + threadIdx.x;

    #pragma unroll
    for (int k = 0; k < ITERS; k++, i += stride) {
        unsigned vec = i & (VECS_PER_ROW - 1);
        unsigned row = i >> 6;                          // b*2048 + s
        unsigned seq = row & (SEQ_LEN - 1);
        unsigned obj = seq >> 3;                        // seq / ATTRIBUTES_NUM
        float4 v = __ldg(&E4[obj * VECS_PER_ROW + vec]);
        __stcs(&out4[i], v);
    }
}

extern "C" void kernel_launch(void* const* d_in, const int* in_sizes, int n_in,
                              void* d_out, int out_size)
{
    // d_in[0] = x (unused), d_in[1] = E_absolute_position [512, 256] fp32
    const float4* E4 = (const float4*)d_in[1];
    float4* out4 = (float4*)d_out;
    ape_kernel<<<BLOCKS, THREADS>>>(E4, out4);
}